// round 2
// baseline (speedup 1.0000x reference)
#include <cuda_runtime.h>

#define N_PTS   20000
#define BB      2
#define PP      2048
#define C_FEAT  64
#define SS      32
#define NQ      (BB*PP)                 // 4096 query points
#define TILE    2048
#define NWARPS  16
#define OUT_F   (BB*(C_FEAT+3)*PP*SS)   // 8781824 floats for new_features

// Scratch (allocation-free rule: __device__ globals)
__device__ float4 g_pts[N_PTS];               // x, y, z, x^2+y^2+z^2
__device__ float  g_featT[N_PTS * C_FEAT];    // transposed features [n][c]

// ---------------------------------------------------------------------------
// Kernel 1: build SoA point array with precomputed squared norm
// ---------------------------------------------------------------------------
__global__ void prep_pts_kernel(const float* __restrict__ xyz) {
    int i = blockIdx.x * 256 + threadIdx.x;
    if (i < N_PTS) {
        float x = xyz[3 * i + 0];
        float y = xyz[3 * i + 1];
        float z = xyz[3 * i + 2];
        float x2 = fmaf(z, z, fmaf(y, y, x * x));
        g_pts[i] = make_float4(x, y, z, x2);
    }
}

// ---------------------------------------------------------------------------
// Kernel 2: transpose features (C, N) -> (N, C) so per-point channels are
// 256B contiguous (gather becomes full-sector LDG.128s in the main kernel)
// ---------------------------------------------------------------------------
__global__ void transpose_feat_kernel(const float* __restrict__ f) {
    __shared__ float tile[32][33];
    int n0 = blockIdx.x * 32;      // 625 blocks * 32 = 20000 exactly
    int c0 = blockIdx.y * 32;      // 2 blocks * 32 = 64 exactly
    int tx = threadIdx.x;          // 32
    int ty = threadIdx.y;          // 8
#pragma unroll
    for (int j = 0; j < 4; j++) {
        int c = c0 + ty + j * 8;
        tile[ty + j * 8][tx] = f[(size_t)c * N_PTS + n0 + tx];
    }
    __syncthreads();
#pragma unroll
    for (int j = 0; j < 4; j++) {
        int n = n0 + ty + j * 8;
        g_featT[(size_t)n * C_FEAT + c0 + tx] = tile[tx][ty + j * 8];
    }
}

// ---------------------------------------------------------------------------
// Kernel 3: fused ball-query + group.
// One warp per query point. Block of 16 warps cooperatively stages point
// tiles in smem (cuts global xyz traffic 16x). Ballot + prefix-popc collects
// the first-32 in-ball indices in ascending order. Then each warp writes its
// 67 output channels (coalesced 128B stores across the s-dimension).
// ---------------------------------------------------------------------------
__global__ void __launch_bounds__(NWARPS * 32)
query_group_kernel(const float* __restrict__ new_xyz,
                   float* __restrict__ out,
                   int write_idn) {
    __shared__ float4 tile[TILE];
    __shared__ int    buf[NWARPS][SS];

    const int tid  = threadIdx.x;
    const int w    = tid >> 5;
    const int lane = tid & 31;
    const int q    = blockIdx.x * NWARPS + w;     // 0..4095
    const int b    = q >> 11;
    const int p    = q & 2047;

    const float qx = new_xyz[3 * q + 0];
    const float qy = new_xyz[3 * q + 1];
    const float qz = new_xyz[3 * q + 2];
    const float q2 = fmaf(qz, qz, fmaf(qy, qy, qx * qx));
    const float R2 = (float)(0.08 * 0.08);        // match reference's python-double -> f32
    const unsigned lmask = (1u << lane) - 1u;

    int count = 0;

    const int NTILES = (N_PTS + TILE - 1) / TILE; // 10
    for (int t = 0; t < NTILES; t++) {
        // cooperative tile load
        for (int i = tid; i < TILE; i += NWARPS * 32) {
            int gi = t * TILE + i;
            // OOB pad: zero coords, huge norm -> d2 = q2 + 1e30 >= R2, never selected
            tile[i] = (gi < N_PTS) ? g_pts[gi] : make_float4(0.f, 0.f, 0.f, 1e30f);
        }
        __syncthreads();

        if (count < SS) {
            const int base = t * TILE;
#pragma unroll 4
            for (int j = 0; j < TILE / 32; j++) {
                float4 pt = tile[j * 32 + lane];
                // replicate reference arithmetic: (q2 + x2) - 2*cross
                float cross = fmaf(qz, pt.z, fmaf(qy, pt.y, qx * pt.x));
                float d2 = fmaf(-2.0f, cross, q2 + pt.w);
                bool pred = d2 < R2;
                unsigned m = __ballot_sync(0xffffffffu, pred);
                if (m) {
                    if (pred) {
                        int slot = count + __popc(m & lmask);
                        if (slot < SS) buf[w][slot] = base + j * 32 + lane;
                    }
                    count += __popc(m);
                    if (count >= SS) break;   // warp early-exit
                }
            }
        }
        __syncthreads();   // block-wide: tile reuse ordering across warps
    }
    __syncwarp();          // explicit intra-warp visibility of buf[w][*] writes

    // --- selection epilogue (matches reference padding semantics) ---
    int cnt   = min(count, SS);
    int first = (cnt > 0) ? buf[w][0] : 0;
    int sel   = (lane < cnt) ? buf[w][lane] : first;
    float idnv = (cnt == 0 || lane < cnt) ? 1.0f : 0.0f;

    // grouped_xyz (channels 0..2): xyz[sel] - query
    float4 ps = g_pts[sel];
    const size_t cs = (size_t)PP * SS;                       // channel stride
    size_t ob = (((size_t)b * (C_FEAT + 3)) * PP + p) * SS + lane;
    out[ob + 0 * cs] = ps.x - qx;
    out[ob + 1 * cs] = ps.y - qy;
    out[ob + 2 * cs] = ps.z - qz;

    // grouped_features (channels 3..66): 16 x LDG.128 per lane, coalesced STG
    const float4* __restrict__ ft = (const float4*)g_featT;
    int fb = sel * (C_FEAT / 4);
    size_t o = ob + 3 * cs;
#pragma unroll
    for (int g = 0; g < C_FEAT / 4; g++) {
        float4 v = ft[fb + g];
        out[o] = v.x; o += cs;
        out[o] = v.y; o += cs;
        out[o] = v.z; o += cs;
        out[o] = v.w; o += cs;
    }

    // idn tail (1/0 written in output dtype; guarded on buffer size)
    if (write_idn)
        out[(size_t)OUT_F + (size_t)q * SS + lane] = idnv;
}

// ---------------------------------------------------------------------------
extern "C" void kernel_launch(void* const* d_in, const int* in_sizes, int n_in,
                              void* d_out, int out_size) {
    const float* xyz      = (const float*)d_in[0];   // (20000, 3)
    const float* new_xyz  = (const float*)d_in[1];   // (2, 2048, 3)
    const float* features = (const float*)d_in[2];   // (64, 20000)
    float* out = (float*)d_out;

    prep_pts_kernel<<<(N_PTS + 255) / 256, 256>>>(xyz);

    dim3 tb(32, 8);
    dim3 tg(N_PTS / 32, C_FEAT / 32);                // 625 x 2
    transpose_feat_kernel<<<tg, tb>>>(features);

    int write_idn = (out_size >= OUT_F + NQ * SS) ? 1 : 0;
    query_group_kernel<<<NQ / NWARPS, NWARPS * 32>>>(new_xyz, out, write_idn);
}

// round 3
// speedup vs baseline: 1.9957x; 1.9957x over previous
#include <cuda_runtime.h>

#define N_PTS   20000
#define BB      2
#define PP      2048
#define C_FEAT  64
#define SS      32
#define NQ      (BB*PP)                 // 4096 query points
#define OUT_F   (BB*(C_FEAT+3)*PP*SS)   // 8781824 floats for new_features
#define G       12                      // grid dim: 1/12 = 0.0833 >= R = 0.08
#define NCELLS  (G*G*G)                 // 1728
#define MAXBUF  128                     // in-ball cap per query (lambda ~ 43)

// Scratch (allocation-free rule: __device__ globals)
__device__ float4 g_pts[N_PTS];               // x, y, z, |p|^2 (original order)
__device__ int    g_pt_cell[N_PTS];
__device__ int    g_cell_count[NCELLS];       // zeroed via memset node
__device__ int    g_cell_start[NCELLS + 1];
__device__ int    g_cell_cursor[NCELLS];
__device__ float4 g_sorted_pts[N_PTS];        // cell-sorted
__device__ int    g_sorted_idx[N_PTS];        // original index per sorted slot
__device__ float  g_featT[N_PTS * C_FEAT];    // transposed features [n][c]

// ---------------------------------------------------------------------------
// K1: SoA points + squared norm + cell id + cell histogram
// ---------------------------------------------------------------------------
__global__ void prep_hist_kernel(const float* __restrict__ xyz) {
    int i = blockIdx.x * 256 + threadIdx.x;
    if (i < N_PTS) {
        float x = xyz[3 * i + 0];
        float y = xyz[3 * i + 1];
        float z = xyz[3 * i + 2];
        float n2 = fmaf(z, z, fmaf(y, y, x * x));
        g_pts[i] = make_float4(x, y, z, n2);
        int cx = min(G - 1, max(0, (int)(x * G)));
        int cy = min(G - 1, max(0, (int)(y * G)));
        int cz = min(G - 1, max(0, (int)(z * G)));
        int cell = (cz * G + cy) * G + cx;
        g_pt_cell[i] = cell;
        atomicAdd(&g_cell_count[cell], 1);
    }
}

// ---------------------------------------------------------------------------
// K2: block 0 = exclusive scan of cell counts (1728 cells, 256 thr x 7);
//     blocks 1..1250 = feature transpose (C,N) -> (N,C)
// ---------------------------------------------------------------------------
__global__ void __launch_bounds__(256)
scan_transpose_kernel(const float* __restrict__ f) {
    if (blockIdx.x == 0) {
        __shared__ int spart[256];
        int t = threadIdx.x;
        int local[7];
        int s = 0;
#pragma unroll
        for (int r = 0; r < 7; r++) {
            int idx = t * 7 + r;
            int v = (idx < NCELLS) ? g_cell_count[idx] : 0;
            local[r] = s;                 // exclusive prefix within thread
            s += v;
        }
        spart[t] = s;
        __syncthreads();
        for (int off = 1; off < 256; off <<= 1) {
            int v = (t >= off) ? spart[t - off] : 0;
            __syncthreads();
            spart[t] += v;
            __syncthreads();
        }
        int toff = (t > 0) ? spart[t - 1] : 0;
#pragma unroll
        for (int r = 0; r < 7; r++) {
            int idx = t * 7 + r;
            if (idx <= NCELLS) {
                int st = toff + local[r];
                g_cell_start[idx] = st;
                if (idx < NCELLS) g_cell_cursor[idx] = st;
            }
        }
    } else {
        __shared__ float tile[32][33];
        int t  = blockIdx.x - 1;          // 0..1249
        int n0 = (t % 625) * 32;
        int c0 = (t / 625) * 32;
        int tx = threadIdx.x & 31;
        int ty = threadIdx.x >> 5;        // 0..7
#pragma unroll
        for (int j = 0; j < 4; j++) {
            int c = c0 + ty + j * 8;
            tile[ty + j * 8][tx] = f[(size_t)c * N_PTS + n0 + tx];
        }
        __syncthreads();
#pragma unroll
        for (int j = 0; j < 4; j++) {
            int n = n0 + ty + j * 8;
            g_featT[(size_t)n * C_FEAT + c0 + tx] = tile[tx][ty + j * 8];
        }
    }
}

// ---------------------------------------------------------------------------
// K3: scatter points into cell-sorted order
// ---------------------------------------------------------------------------
__global__ void scatter_kernel() {
    int i = blockIdx.x * 256 + threadIdx.x;
    if (i < N_PTS) {
        int cell = g_pt_cell[i];
        int pos = atomicAdd(&g_cell_cursor[cell], 1);
        g_sorted_pts[pos] = g_pts[i];
        g_sorted_idx[pos] = i;
    }
}

// ---------------------------------------------------------------------------
// Warp-collective bitonic sort of 128 int keys (4 regs/lane, e = j*32+lane).
// Ascending; smallest 32 land in k[0] across lanes 0..31.
// ---------------------------------------------------------------------------
__device__ __forceinline__ void bitonic128(int k[4], int lane) {
#pragma unroll
    for (int size = 2; size <= 128; size <<= 1) {
#pragma unroll
        for (int stride = size >> 1; stride > 0; stride >>= 1) {
            if (stride >= 32) {
                int sj = stride >> 5;     // 1 or 2
#pragma unroll
                for (int j = 0; j < 4; j++) {
                    if ((j & sj) == 0) {
                        int pj = j | sj;
                        int e = j * 32 + lane;
                        bool up = ((e & size) == 0);
                        int a = k[j], b = k[pj];
                        int lo = min(a, b), hi = max(a, b);
                        k[j]  = up ? lo : hi;
                        k[pj] = up ? hi : lo;
                    }
                }
            } else {
#pragma unroll
                for (int j = 0; j < 4; j++) {
                    int e = j * 32 + lane;
                    bool up = ((e & size) == 0);
                    int other = __shfl_xor_sync(0xffffffffu, k[j], stride);
                    bool keepMin = (((lane & stride) == 0) == up);
                    k[j] = keepMin ? min(k[j], other) : max(k[j], other);
                }
            }
        }
    }
}

// ---------------------------------------------------------------------------
// K4: grid ball-query + group. One warp per query; 27 neighbor cells give
// ~313 candidates (64x fewer than brute force). Ballot-collect in-ball
// original indices, bitonic-sort, take 32 smallest, then fused gather/write.
// ---------------------------------------------------------------------------
__global__ void __launch_bounds__(256)
query_group_kernel(const float* __restrict__ new_xyz,
                   float* __restrict__ out,
                   int write_idn) {
    __shared__ int buf[8][MAXBUF];

    const int tid  = threadIdx.x;
    const int w    = tid >> 5;
    const int lane = tid & 31;
    const int q    = blockIdx.x * 8 + w;          // 0..4095
    const int b    = q >> 11;
    const int p    = q & 2047;

    const float qx = new_xyz[3 * q + 0];
    const float qy = new_xyz[3 * q + 1];
    const float qz = new_xyz[3 * q + 2];
    const float q2 = fmaf(qz, qz, fmaf(qy, qy, qx * qx));
    const float R2 = (float)(0.08 * 0.08);
    const unsigned lmask = (1u << lane) - 1u;

    const int cxq = min(G - 1, max(0, (int)(qx * G)));
    const int cyq = min(G - 1, max(0, (int)(qy * G)));
    const int czq = min(G - 1, max(0, (int)(qz * G)));
    const int xlo = max(cxq - 1, 0), xhi = min(cxq + 1, G - 1);
    const int ylo = max(cyq - 1, 0), yhi = min(cyq + 1, G - 1);
    const int zlo = max(czq - 1, 0), zhi = min(czq + 1, G - 1);

    int count = 0;
    // x-adjacent cells are contiguous -> merge into one range per (z,y): 9 ranges
    for (int cz = zlo; cz <= zhi; cz++) {
        for (int cy = ylo; cy <= yhi; cy++) {
            int rowbase = (cz * G + cy) * G;
            int rs = g_cell_start[rowbase + xlo];
            int re = g_cell_start[rowbase + xhi + 1];
            for (int base = rs; base < re; base += 32) {
                int i = base + lane;
                bool v = i < re;
                float4 pt = v ? g_sorted_pts[i] : make_float4(0.f, 0.f, 0.f, 1e30f);
                // reference arithmetic: (q2 + |p|^2) - 2*cross, same FMA shape
                float cross = fmaf(qz, pt.z, fmaf(qy, pt.y, qx * pt.x));
                float d2 = fmaf(-2.0f, cross, q2 + pt.w);
                bool pred = v && (d2 < R2);
                unsigned m = __ballot_sync(0xffffffffu, pred);
                if (pred) {
                    int slot = count + __popc(m & lmask);
                    if (slot < MAXBUF) buf[w][slot] = g_sorted_idx[i];
                }
                count += __popc(m);
            }
        }
    }
    __syncwarp();

    int nbuf = min(count, MAXBUF);
    int k[4];
#pragma unroll
    for (int j = 0; j < 4; j++) {
        int e = j * 32 + lane;
        k[j] = (e < nbuf) ? buf[w][e] : 0x7fffffff;
    }
    bitonic128(k, lane);
    // ranks 0..31 live in k[0] across lanes

    int first = __shfl_sync(0xffffffffu, k[0], 0);
    int c32   = min(count, SS);
    int sel   = (lane < c32) ? k[0] : ((count > 0) ? first : 0);
    float idnv = (count == 0 || lane < count) ? 1.0f : 0.0f;

    // grouped_xyz (channels 0..2): xyz[sel] - query
    float4 ps = g_pts[sel];
    const size_t cs = (size_t)PP * SS;
    size_t ob = (((size_t)b * (C_FEAT + 3)) * PP + p) * SS + lane;
    out[ob + 0 * cs] = ps.x - qx;
    out[ob + 1 * cs] = ps.y - qy;
    out[ob + 2 * cs] = ps.z - qz;

    // grouped_features (channels 3..66): 16 x LDG.128 per lane (featT in L2)
    const float4* __restrict__ ft = (const float4*)g_featT;
    int fb = sel * (C_FEAT / 4);
    size_t o = ob + 3 * cs;
#pragma unroll
    for (int g = 0; g < C_FEAT / 4; g++) {
        float4 vv = ft[fb + g];
        out[o] = vv.x; o += cs;
        out[o] = vv.y; o += cs;
        out[o] = vv.z; o += cs;
        out[o] = vv.w; o += cs;
    }

    if (write_idn)
        out[(size_t)OUT_F + (size_t)q * SS + lane] = idnv;
}

// ---------------------------------------------------------------------------
extern "C" void kernel_launch(void* const* d_in, const int* in_sizes, int n_in,
                              void* d_out, int out_size) {
    const float* xyz      = (const float*)d_in[0];   // (20000, 3)
    const float* new_xyz  = (const float*)d_in[1];   // (2, 2048, 3)
    const float* features = (const float*)d_in[2];   // (64, 20000)
    float* out = (float*)d_out;

    void* cnt_ptr = nullptr;
    cudaGetSymbolAddress(&cnt_ptr, g_cell_count);
    cudaMemsetAsync(cnt_ptr, 0, NCELLS * sizeof(int));

    prep_hist_kernel<<<(N_PTS + 255) / 256, 256>>>(xyz);
    scan_transpose_kernel<<<1 + 625 * 2, 256>>>(features);
    scatter_kernel<<<(N_PTS + 255) / 256, 256>>>();

    int write_idn = (out_size >= OUT_F + NQ * SS) ? 1 : 0;
    query_group_kernel<<<NQ / 8, 256>>>(new_xyz, out, write_idn);
}